// round 13
// baseline (speedup 1.0000x reference)
#include <cuda_runtime.h>
#include <math.h>
#include <stdint.h>

#define B 16384
#define C 100
#define D 512
#define Z 128
#define BETA 50000000.0
#define EPSF 1e-8f

#define GRID        148
#define THREADS     416          // 12 consumer warps + 1 producer warp
#define NCONS       12
#define RPS         4            // rows per stage
#define NSTAGE      (B / RPS)    // 4096
#define NBUF        3

// stage layout in floats
#define OFF_TUBE(pair, al) (((pair) * 2 + (al)) * (RPS * D))   // 8 x 2048 floats
#define OFF_MU   16384
#define OFF_LV   16896
#define OFF_F    17408
#define OFF_LB   17808
#define STAGE_FLOATS 18208
#define STAGE_BYTES  (STAGE_FLOATS * 4)          // 72832
// barriers: full[0..2] then empty[0..2]
#define SMEM_BYTES   (NBUF * STAGE_BYTES + 64)

__device__ double g_acc[3] = {0.0, 0.0, 0.0};
__device__ unsigned g_count = 0u;

__device__ __forceinline__ uint32_t smem_u32(const void* p) {
    uint32_t a;
    asm("{ .reg .u64 t; cvta.to.shared.u64 t, %1; cvt.u32.u64 %0, t; }" : "=r"(a) : "l"(p));
    return a;
}

__device__ __forceinline__ void bulk_cp(uint32_t dst, const void* src, uint32_t bytes, uint32_t bar) {
    asm volatile("cp.async.bulk.shared::cluster.global.mbarrier::complete_tx::bytes [%0], [%1], %2, [%3];"
                 :: "r"(dst), "l"(src), "r"(bytes), "r"(bar) : "memory");
}

__device__ __forceinline__ void mbar_wait(uint32_t bar, uint32_t parity) {
    uint32_t done;
    asm volatile("{ .reg .pred p; mbarrier.try_wait.parity.acquire.cta.shared::cta.b64 p, [%1], %2; selp.b32 %0, 1, 0, p; }"
                 : "=r"(done) : "r"(bar), "r"(parity) : "memory");
    if (!done) {
        asm volatile("{ .reg .pred P1; WL%=: mbarrier.try_wait.parity.acquire.cta.shared::cta.b64 P1, [%0], %1, 0x989680; @P1 bra.uni WD%=; bra.uni WL%=; WD%=: }"
                     :: "r"(bar), "r"(parity) : "memory");
    }
}

__device__ __forceinline__ void mbar_arrive(uint32_t bar) {
    asm volatile("mbarrier.arrive.release.cta.shared::cta.b64 _, [%0];" :: "r"(bar) : "memory");
}

__device__ __forceinline__ float warp_sum(float v) {
#pragma unroll
    for (int o = 16; o; o >>= 1) v += __shfl_xor_sync(0xffffffffu, v, o);
    return v;
}

__device__ __forceinline__ float tube_scalar(float dot, float pp, float gg) {
    float p = sqrtf(pp);
    float g = sqrtf(gg);
    float denom = p * g;
    float cosine = (denom == 0.f) ? 0.f : (dot / denom);
    float s_s = 1.f - cosine * cosine;
    float sine = (s_s < 0.f) ? 0.f : sqrtf((s_s <= 0.f) ? EPSF : s_s);
    float gd = (g == 0.f) ? (g + EPSF) : g;
    float pc = p * cosine;
    float r_all = pc / gd;
    float ps = p * sine;
    float ds;
    if (r_all >= 1.f)       ds = 0.5f * (ps + fabsf(g - pc));
    else if (r_all >= 0.f)  ds = ps + fabsf(g - pc);
    else                    ds = 1.5f * fabsf(pc - g - ps);
    return -__logf(tanhf(1.f / ds));   // ds==0 -> inf -> tanh=1 -> 0, matches jax
}

extern __shared__ float smem[];

__device__ __forceinline__ void issue_stage(
    int s, uint32_t dst, uint32_t bar,
    const float* const* atts, const float* const* labs,
    const float* mu, const float* lv, const float* fusion, const float* labels)
{
    asm volatile("mbarrier.arrive.expect_tx.shared.b64 _, [%0], %1;"
                 :: "r"(bar), "r"((uint32_t)STAGE_BYTES) : "memory");
#pragma unroll
    for (int j = 0; j < 4; j++) {
        bulk_cp(dst + OFF_TUBE(j, 0) * 4, atts[j] + (long)s * (RPS * D), RPS * D * 4, bar);
        bulk_cp(dst + OFF_TUBE(j, 1) * 4, labs[j] + (long)s * (RPS * D), RPS * D * 4, bar);
    }
    bulk_cp(dst + OFF_MU * 4, mu     + (long)s * (RPS * Z), RPS * Z * 4, bar);
    bulk_cp(dst + OFF_LV * 4, lv     + (long)s * (RPS * Z), RPS * Z * 4, bar);
    bulk_cp(dst + OFF_F  * 4, fusion + (long)s * (RPS * C), RPS * C * 4, bar);
    bulk_cp(dst + OFF_LB * 4, labels + (long)s * (RPS * C), RPS * C * 4, bar);
}

__global__ void __launch_bounds__(THREADS, 1)
loss_kernel(const float* __restrict__ fusion,
            const float* __restrict__ comple,
            const float* __restrict__ labels,
            const float* __restrict__ lab_enc,
            const float* __restrict__ xA,  const float* __restrict__ xAr,
            const float* __restrict__ xB,  const float* __restrict__ xBr,
            const float* __restrict__ xC,  const float* __restrict__ xCr,
            const float* __restrict__ mu,  const float* __restrict__ lv,
            float* __restrict__ out)
{
    const int tid  = threadIdx.x;
    const int warp = tid >> 5;
    const int lane = tid & 31;
    const int bid  = blockIdx.x;

    const float* atts[4] = { xAr, xBr, xCr, comple };
    const float* labs[4] = { xA,  xB,  xC,  lab_enc };

    const uint32_t smem_base  = smem_u32(smem);
    const uint32_t full_base  = smem_base + NBUF * STAGE_BYTES;
    const uint32_t empty_base = full_base + NBUF * 8;

    if (tid == 0) {
#pragma unroll
        for (int k = 0; k < NBUF; k++) {
            asm volatile("mbarrier.init.shared.b64 [%0], 1;"  :: "r"(full_base  + k * 8) : "memory");
            asm volatile("mbarrier.init.shared.b64 [%0], %1;" :: "r"(empty_base + k * 8), "r"(NCONS) : "memory");
        }
        asm volatile("fence.proxy.async.shared::cta;" ::: "memory");
    }
    __syncthreads();

    const int nIter = (NSTAGE - bid + GRID - 1) / GRID;   // 27 or 28, >= NBUF

    float tube = 0.f, ce = 0.f, kl = 0.f;

    if (warp == NCONS) {
        // ---------------- producer warp ----------------
        if (lane == 0) {
#pragma unroll
            for (int k = 0; k < NBUF; k++)
                issue_stage(bid + k * GRID, smem_base + k * STAGE_BYTES, full_base + k * 8,
                            atts, labs, mu, lv, fusion, labels);
            for (int nx = NBUF; nx < nIter; nx++) {
                const int buf = nx % NBUF;
                const uint32_t parity = ((nx / NBUF) - 1) & 1;
                mbar_wait(empty_base + buf * 8, parity);
                asm volatile("fence.proxy.async.shared::cta;" ::: "memory");
                issue_stage(bid + nx * GRID, smem_base + buf * STAGE_BYTES, full_base + buf * 8,
                            atts, labs, mu, lv, fusion, labels);
            }
        }
    } else {
        // ---------------- consumer warps (0..11): 2 tasks each, EARLY buffer release ----------------
        int buf = 0;
        unsigned parity = 0;
        for (int it = 0; it < nIter; it++) {
            mbar_wait(full_base + buf * 8, parity);
            const float* bufp = smem + buf * STAGE_FLOATS;
            const uint32_t ebar = empty_base + buf * 8;

            if (warp < 8) {
                // two tube tasks t0=warp*2, t1=warp*2+1 (row=t>>2, pair=t&3)
                const int t0 = warp * 2;
                const float4* a40 = (const float4*)(bufp + OFF_TUBE(t0 & 3, 0)       + (t0 >> 2) * D);
                const float4* g40 = (const float4*)(bufp + OFF_TUBE(t0 & 3, 1)       + (t0 >> 2) * D);
                const float4* a41 = (const float4*)(bufp + OFF_TUBE((t0 + 1) & 3, 0) + ((t0 + 1) >> 2) * D);
                const float4* g41 = (const float4*)(bufp + OFF_TUBE((t0 + 1) & 3, 1) + ((t0 + 1) >> 2) * D);
                float dot0 = 0.f, pp0 = 0.f, gg0 = 0.f;
                float dot1 = 0.f, pp1 = 0.f, gg1 = 0.f;
#pragma unroll
                for (int i = 0; i < 4; i++) {
                    float4 a = a40[lane + 32 * i];
                    float4 g = g40[lane + 32 * i];
                    dot0 += a.x * g.x + a.y * g.y + a.z * g.z + a.w * g.w;
                    pp0  += a.x * a.x + a.y * a.y + a.z * a.z + a.w * a.w;
                    gg0  += g.x * g.x + g.y * g.y + g.z * g.z + g.w * g.w;
                    a = a41[lane + 32 * i];
                    g = g41[lane + 32 * i];
                    dot1 += a.x * g.x + a.y * g.y + a.z * g.z + a.w * g.w;
                    pp1  += a.x * a.x + a.y * a.y + a.z * a.z + a.w * a.w;
                    gg1  += g.x * g.x + g.y * g.y + g.z * g.z + g.w * g.w;
                }
                __syncwarp();
                if (lane == 0) mbar_arrive(ebar);    // buffer free: reductions are register-only
                dot0 = warp_sum(dot0); pp0 = warp_sum(pp0); gg0 = warp_sum(gg0);
                dot1 = warp_sum(dot1); pp1 = warp_sum(pp1); gg1 = warp_sum(gg1);
                tube += tube_scalar(dot0, pp0, gg0) + tube_scalar(dot1, pp1, gg1);
            } else if (warp < 10) {
                // KL for rows 2*(warp-8), 2*(warp-8)+1
                const int r0 = (warp - 8) * 2;
                float4 m0 = ((const float4*)(bufp + OFF_MU + r0 * Z))[lane];
                float4 l0 = ((const float4*)(bufp + OFF_LV + r0 * Z))[lane];
                float4 m1 = ((const float4*)(bufp + OFF_MU + (r0 + 1) * Z))[lane];
                float4 l1 = ((const float4*)(bufp + OFF_LV + (r0 + 1) * Z))[lane];
                __syncwarp();
                if (lane == 0) mbar_arrive(ebar);
                float k = (1.f + l0.x - m0.x * m0.x - __expf(l0.x))
                        + (1.f + l0.y - m0.y * m0.y - __expf(l0.y))
                        + (1.f + l0.z - m0.z * m0.z - __expf(l0.z))
                        + (1.f + l0.w - m0.w * m0.w - __expf(l0.w))
                        + (1.f + l1.x - m1.x * m1.x - __expf(l1.x))
                        + (1.f + l1.y - m1.y * m1.y - __expf(l1.y))
                        + (1.f + l1.z - m1.z * m1.z - __expf(l1.z))
                        + (1.f + l1.w - m1.w * m1.w - __expf(l1.w));
                kl += warp_sum(k);
            } else {
                // CE for rows 2*(warp-10), 2*(warp-10)+1; keep fusion vals in regs
                const int r0 = (warp - 10) * 2;
                float fv0[4], fv1[4];
                float fmax0 = -INFINITY, lmax0 = -INFINITY;
                float fmax1 = -INFINITY, lmax1 = -INFINITY;
                int lidx0 = 0x7fffffff, lidx1 = 0x7fffffff;
#pragma unroll
                for (int q = 0; q < 4; q++) {
                    int i = lane + 32 * q;
                    fv0[q] = -INFINITY; fv1[q] = -INFINITY;
                    if (i < C) {
                        fv0[q] = (bufp + OFF_F + r0 * C)[i];
                        fv1[q] = (bufp + OFF_F + (r0 + 1) * C)[i];
                        float lb0 = (bufp + OFF_LB + r0 * C)[i];
                        float lb1 = (bufp + OFF_LB + (r0 + 1) * C)[i];
                        fmax0 = fmaxf(fmax0, fv0[q]);
                        fmax1 = fmaxf(fmax1, fv1[q]);
                        if (lb0 > lmax0 || (lb0 == lmax0 && i < lidx0)) { lmax0 = lb0; lidx0 = i; }
                        if (lb1 > lmax1 || (lb1 == lmax1 && i < lidx1)) { lmax1 = lb1; lidx1 = i; }
                    }
                }
                __syncwarp();
                if (lane == 0) mbar_arrive(ebar);
#pragma unroll
                for (int o = 16; o; o >>= 1) {
                    fmax0 = fmaxf(fmax0, __shfl_xor_sync(0xffffffffu, fmax0, o));
                    fmax1 = fmaxf(fmax1, __shfl_xor_sync(0xffffffffu, fmax1, o));
                    float ol0 = __shfl_xor_sync(0xffffffffu, lmax0, o);
                    int   oi0 = __shfl_xor_sync(0xffffffffu, lidx0, o);
                    if (ol0 > lmax0 || (ol0 == lmax0 && oi0 < lidx0)) { lmax0 = ol0; lidx0 = oi0; }
                    float ol1 = __shfl_xor_sync(0xffffffffu, lmax1, o);
                    int   oi1 = __shfl_xor_sync(0xffffffffu, lidx1, o);
                    if (ol1 > lmax1 || (ol1 == lmax1 && oi1 < lidx1)) { lmax1 = ol1; lidx1 = oi1; }
                }
                float se0 = 0.f, se1 = 0.f;
#pragma unroll
                for (int q = 0; q < 4; q++) {
                    se0 += (fv0[q] == -INFINITY) ? 0.f : __expf(fv0[q] - fmax0);
                    se1 += (fv1[q] == -INFINITY) ? 0.f : __expf(fv1[q] - fmax1);
                }
                se0 = warp_sum(se0);
                se1 = warp_sum(se1);
                int ts0 = lidx0 >> 5;
                float fsel0 = (ts0 == 0) ? fv0[0] : (ts0 == 1) ? fv0[1] : (ts0 == 2) ? fv0[2] : fv0[3];
                float ft0 = __shfl_sync(0xffffffffu, fsel0, lidx0 & 31);
                int ts1 = lidx1 >> 5;
                float fsel1 = (ts1 == 0) ? fv1[0] : (ts1 == 1) ? fv1[1] : (ts1 == 2) ? fv1[2] : fv1[3];
                float ft1 = __shfl_sync(0xffffffffu, fsel1, lidx1 & 31);
                ce += -(ft0 - fmax0 - __logf(se0)) - (ft1 - fmax1 - __logf(se1));
            }

            if (++buf == NBUF) { buf = 0; parity ^= 1u; }
        }
    }

    // ---- block reduce + last-block finalize ----
    __shared__ float sT[13], sC[13], sK[13];
    if (lane == 0) { sT[warp] = tube; sC[warp] = ce; sK[warp] = kl; }
    __syncthreads();
    if (tid == 0) {
        float t = 0.f, c = 0.f, k = 0.f;
#pragma unroll
        for (int i = 0; i < NCONS; i++) { t += sT[i]; c += sC[i]; k += sK[i]; }
        atomicAdd(&g_acc[0], (double)t);
        atomicAdd(&g_acc[1], (double)c);
        atomicAdd(&g_acc[2], (double)k);
        __threadfence();
        unsigned prev = atomicAdd(&g_count, 1u);
        if (prev == gridDim.x - 1) {
            __threadfence();
            double tubeS = g_acc[0] / (double)B;                         // ALPHA = 1
            double ceS   = g_acc[1] / (double)B;
            double klS   = -0.5 * BETA * (g_acc[2] / ((double)B * (double)Z));
            out[0] = (float)(tubeS + ceS + klS);
            g_acc[0] = 0.0; g_acc[1] = 0.0; g_acc[2] = 0.0;
            g_count = 0u;
            __threadfence();
        }
    }
}

extern "C" void kernel_launch(void* const* d_in, const int* in_sizes, int n_in,
                              void* d_out, int out_size) {
    const float* fusion  = (const float*)d_in[0];
    const float* comple  = (const float*)d_in[1];
    const float* labels  = (const float*)d_in[2];
    const float* lab_enc = (const float*)d_in[3];
    const float* xA      = (const float*)d_in[4];
    const float* xAr     = (const float*)d_in[5];
    const float* xB      = (const float*)d_in[6];
    const float* xBr     = (const float*)d_in[7];
    const float* xC      = (const float*)d_in[8];
    const float* xCr     = (const float*)d_in[9];
    const float* mu      = (const float*)d_in[10];
    const float* lv      = (const float*)d_in[11];
    float* out = (float*)d_out;

    static int configured = 0;
    if (!configured) {
        cudaFuncSetAttribute(loss_kernel, cudaFuncAttributeMaxDynamicSharedMemorySize, SMEM_BYTES);
        configured = 1;
    }
    loss_kernel<<<GRID, THREADS, SMEM_BYTES>>>(fusion, comple, labels, lab_enc,
                                               xA, xAr, xB, xBr, xC, xCr, mu, lv, out);
}

// round 14
// speedup vs baseline: 1.0246x; 1.0246x over previous
#include <cuda_runtime.h>
#include <math.h>
#include <stdint.h>

#define B 16384
#define C 100
#define D 512
#define Z 128
#define BETA 50000000.0
#define EPSF 1e-8f

#define GRID        148
#define THREADS     800          // 24 consumer warps + 1 producer warp
#define NCONS       24
#define RPS         4            // rows per stage
#define NSTAGE      (B / RPS)    // 4096
#define NBUF        3

// stage layout in floats
#define OFF_TUBE(pair, al) (((pair) * 2 + (al)) * (RPS * D))   // 8 x 2048 floats
#define OFF_MU   16384
#define OFF_LV   16896
#define OFF_F    17408
#define OFF_LB   17808
#define STAGE_FLOATS 18208
#define STAGE_BYTES  (STAGE_FLOATS * 4)          // 72832
// barriers: full[0..2] then empty[0..2]
#define SMEM_BYTES   (NBUF * STAGE_BYTES + 64)

__device__ double g_acc[3] = {0.0, 0.0, 0.0};
__device__ unsigned g_count = 0u;

__device__ __forceinline__ uint32_t smem_u32(const void* p) {
    uint32_t a;
    asm("{ .reg .u64 t; cvta.to.shared.u64 t, %1; cvt.u32.u64 %0, t; }" : "=r"(a) : "l"(p));
    return a;
}

__device__ __forceinline__ void bulk_cp(uint32_t dst, const void* src, uint32_t bytes, uint32_t bar) {
    asm volatile("cp.async.bulk.shared::cluster.global.mbarrier::complete_tx::bytes [%0], [%1], %2, [%3];"
                 :: "r"(dst), "l"(src), "r"(bytes), "r"(bar) : "memory");
}

__device__ __forceinline__ void mbar_wait(uint32_t bar, uint32_t parity) {
    uint32_t done;
    asm volatile("{ .reg .pred p; mbarrier.try_wait.parity.acquire.cta.shared::cta.b64 p, [%1], %2; selp.b32 %0, 1, 0, p; }"
                 : "=r"(done) : "r"(bar), "r"(parity) : "memory");
    if (!done) {
        asm volatile("{ .reg .pred P1; WL%=: mbarrier.try_wait.parity.acquire.cta.shared::cta.b64 P1, [%0], %1, 0x989680; @P1 bra.uni WD%=; bra.uni WL%=; WD%=: }"
                     :: "r"(bar), "r"(parity) : "memory");
    }
}

__device__ __forceinline__ void mbar_arrive(uint32_t bar) {
    asm volatile("mbarrier.arrive.release.cta.shared::cta.b64 _, [%0];" :: "r"(bar) : "memory");
}

__device__ __forceinline__ float warp_sum(float v) {
#pragma unroll
    for (int o = 16; o; o >>= 1) v += __shfl_xor_sync(0xffffffffu, v, o);
    return v;
}

__device__ __forceinline__ float tube_scalar(float dot, float pp, float gg) {
    float p = sqrtf(pp);
    float g = sqrtf(gg);
    float denom = p * g;
    float cosine = (denom == 0.f) ? 0.f : (dot / denom);
    float s_s = 1.f - cosine * cosine;
    float sine = (s_s < 0.f) ? 0.f : sqrtf((s_s <= 0.f) ? EPSF : s_s);
    float gd = (g == 0.f) ? (g + EPSF) : g;
    float pc = p * cosine;
    float r_all = pc / gd;
    float ps = p * sine;
    float ds;
    if (r_all >= 1.f)       ds = 0.5f * (ps + fabsf(g - pc));
    else if (r_all >= 0.f)  ds = ps + fabsf(g - pc);
    else                    ds = 1.5f * fabsf(pc - g - ps);
    return -__logf(tanhf(1.f / ds));   // ds==0 -> inf -> tanh=1 -> 0, matches jax
}

extern __shared__ float smem[];

__device__ __forceinline__ void issue_stage(
    int s, uint32_t dst, uint32_t bar,
    const float* const* atts, const float* const* labs,
    const float* mu, const float* lv, const float* fusion, const float* labels)
{
    asm volatile("mbarrier.arrive.expect_tx.shared.b64 _, [%0], %1;"
                 :: "r"(bar), "r"((uint32_t)STAGE_BYTES) : "memory");
#pragma unroll
    for (int j = 0; j < 4; j++) {
        bulk_cp(dst + OFF_TUBE(j, 0) * 4, atts[j] + (long)s * (RPS * D), RPS * D * 4, bar);
        bulk_cp(dst + OFF_TUBE(j, 1) * 4, labs[j] + (long)s * (RPS * D), RPS * D * 4, bar);
    }
    bulk_cp(dst + OFF_MU * 4, mu     + (long)s * (RPS * Z), RPS * Z * 4, bar);
    bulk_cp(dst + OFF_LV * 4, lv     + (long)s * (RPS * Z), RPS * Z * 4, bar);
    bulk_cp(dst + OFF_F  * 4, fusion + (long)s * (RPS * C), RPS * C * 4, bar);
    bulk_cp(dst + OFF_LB * 4, labels + (long)s * (RPS * C), RPS * C * 4, bar);
}

__global__ void __launch_bounds__(THREADS, 1)
loss_kernel(const float* __restrict__ fusion,
            const float* __restrict__ comple,
            const float* __restrict__ labels,
            const float* __restrict__ lab_enc,
            const float* __restrict__ xA,  const float* __restrict__ xAr,
            const float* __restrict__ xB,  const float* __restrict__ xBr,
            const float* __restrict__ xC,  const float* __restrict__ xCr,
            const float* __restrict__ mu,  const float* __restrict__ lv,
            float* __restrict__ out)
{
    const int tid  = threadIdx.x;
    const int warp = tid >> 5;
    const int lane = tid & 31;
    const int bid  = blockIdx.x;

    const float* atts[4] = { xAr, xBr, xCr, comple };
    const float* labs[4] = { xA,  xB,  xC,  lab_enc };

    const uint32_t smem_base  = smem_u32(smem);
    const uint32_t full_base  = smem_base + NBUF * STAGE_BYTES;
    const uint32_t empty_base = full_base + NBUF * 8;

    if (tid == 0) {
#pragma unroll
        for (int k = 0; k < NBUF; k++) {
            asm volatile("mbarrier.init.shared.b64 [%0], 1;"  :: "r"(full_base  + k * 8) : "memory");
            asm volatile("mbarrier.init.shared.b64 [%0], %1;" :: "r"(empty_base + k * 8), "r"(NCONS) : "memory");
        }
        asm volatile("fence.proxy.async.shared::cta;" ::: "memory");
    }
    __syncthreads();

    const int nIter = (NSTAGE - bid + GRID - 1) / GRID;   // 27 or 28, >= NBUF

    float tube = 0.f, ce = 0.f, kl = 0.f;

    if (warp == NCONS) {
        // ---------------- producer warp ----------------
        if (lane == 0) {
#pragma unroll
            for (int k = 0; k < NBUF; k++)
                issue_stage(bid + k * GRID, smem_base + k * STAGE_BYTES, full_base + k * 8,
                            atts, labs, mu, lv, fusion, labels);
            for (int nx = NBUF; nx < nIter; nx++) {
                const int buf = nx % NBUF;
                const uint32_t parity = ((nx / NBUF) - 1) & 1;
                mbar_wait(empty_base + buf * 8, parity);
                asm volatile("fence.proxy.async.shared::cta;" ::: "memory");
                issue_stage(bid + nx * GRID, smem_base + buf * STAGE_BYTES, full_base + buf * 8,
                            atts, labs, mu, lv, fusion, labels);
            }
        }
    } else {
        // ---------------- consumer warps (0..23): exactly 1 task per stage ----------------
        int buf = 0;
        unsigned parity = 0;
        for (int it = 0; it < nIter; it++) {
            mbar_wait(full_base + buf * 8, parity);
            const float* bufp = smem + buf * STAGE_FLOATS;

            if (warp < 16) {
                const int row = warp >> 2, pair = warp & 3;
                const float4* a4 = (const float4*)(bufp + OFF_TUBE(pair, 0) + row * D);
                const float4* g4 = (const float4*)(bufp + OFF_TUBE(pair, 1) + row * D);
                float dot = 0.f, pp = 0.f, gg = 0.f;
#pragma unroll
                for (int i = 0; i < 4; i++) {
                    float4 a = a4[lane + 32 * i];
                    float4 g = g4[lane + 32 * i];
                    dot += a.x * g.x + a.y * g.y + a.z * g.z + a.w * g.w;
                    pp  += a.x * a.x + a.y * a.y + a.z * a.z + a.w * a.w;
                    gg  += g.x * g.x + g.y * g.y + g.z * g.z + g.w * g.w;
                }
                dot = warp_sum(dot);
                pp  = warp_sum(pp);
                gg  = warp_sum(gg);
                tube += tube_scalar(dot, pp, gg);
            } else if (warp < 20) {
                const int row = warp - 16;
                float4 m = ((const float4*)(bufp + OFF_MU + row * Z))[lane];
                float4 l = ((const float4*)(bufp + OFF_LV + row * Z))[lane];
                float k = (1.f + l.x - m.x * m.x - __expf(l.x))
                        + (1.f + l.y - m.y * m.y - __expf(l.y))
                        + (1.f + l.z - m.z * m.z - __expf(l.z))
                        + (1.f + l.w - m.w * m.w - __expf(l.w));
                kl += warp_sum(k);
            } else {
                const int row = warp - 20;
                const float* f  = bufp + OFF_F  + row * C;
                const float* lb = bufp + OFF_LB + row * C;
                float fmax = -INFINITY, lmax = -INFINITY;
                int lidx = 0x7fffffff;
#pragma unroll
                for (int q = 0; q < 4; q++) {
                    int i = lane + 32 * q;
                    if (i < C) {
                        float fv  = f[i];
                        float lvv = lb[i];
                        fmax = fmaxf(fmax, fv);
                        if (lvv > lmax || (lvv == lmax && i < lidx)) { lmax = lvv; lidx = i; }
                    }
                }
#pragma unroll
                for (int o = 16; o; o >>= 1) {
                    fmax = fmaxf(fmax, __shfl_xor_sync(0xffffffffu, fmax, o));
                    float ol = __shfl_xor_sync(0xffffffffu, lmax, o);
                    int   oi = __shfl_xor_sync(0xffffffffu, lidx, o);
                    if (ol > lmax || (ol == lmax && oi < lidx)) { lmax = ol; lidx = oi; }
                }
                float se = 0.f;
#pragma unroll
                for (int q = 0; q < 4; q++) {
                    int i = lane + 32 * q;
                    if (i < C) se += __expf(f[i] - fmax);
                }
                se = warp_sum(se);
                ce += -(f[lidx] - fmax - __logf(se));
            }

            __syncwarp();
            if (lane == 0) mbar_arrive(empty_base + buf * 8);   // free this buffer

            if (++buf == NBUF) { buf = 0; parity ^= 1u; }
        }
    }

    // ---- block reduce + last-block finalize ----
    __shared__ float sT[25], sC[25], sK[25];
    if (lane == 0) { sT[warp] = tube; sC[warp] = ce; sK[warp] = kl; }
    __syncthreads();
    if (tid == 0) {
        float t = 0.f, c = 0.f, k = 0.f;
#pragma unroll
        for (int i = 0; i < NCONS; i++) { t += sT[i]; c += sC[i]; k += sK[i]; }
        atomicAdd(&g_acc[0], (double)t);
        atomicAdd(&g_acc[1], (double)c);
        atomicAdd(&g_acc[2], (double)k);
        __threadfence();
        unsigned prev = atomicAdd(&g_count, 1u);
        if (prev == gridDim.x - 1) {
            __threadfence();
            double tubeS = g_acc[0] / (double)B;                         // ALPHA = 1
            double ceS   = g_acc[1] / (double)B;
            double klS   = -0.5 * BETA * (g_acc[2] / ((double)B * (double)Z));
            out[0] = (float)(tubeS + ceS + klS);
            g_acc[0] = 0.0; g_acc[1] = 0.0; g_acc[2] = 0.0;
            g_count = 0u;
            __threadfence();
        }
    }
}

extern "C" void kernel_launch(void* const* d_in, const int* in_sizes, int n_in,
                              void* d_out, int out_size) {
    const float* fusion  = (const float*)d_in[0];
    const float* comple  = (const float*)d_in[1];
    const float* labels  = (const float*)d_in[2];
    const float* lab_enc = (const float*)d_in[3];
    const float* xA      = (const float*)d_in[4];
    const float* xAr     = (const float*)d_in[5];
    const float* xB      = (const float*)d_in[6];
    const float* xBr     = (const float*)d_in[7];
    const float* xC      = (const float*)d_in[8];
    const float* xCr     = (const float*)d_in[9];
    const float* mu      = (const float*)d_in[10];
    const float* lv      = (const float*)d_in[11];
    float* out = (float*)d_out;

    static int configured = 0;
    if (!configured) {
        cudaFuncSetAttribute(loss_kernel, cudaFuncAttributeMaxDynamicSharedMemorySize, SMEM_BYTES);
        configured = 1;
    }
    loss_kernel<<<GRID, THREADS, SMEM_BYTES>>>(fusion, comple, labels, lab_enc,
                                               xA, xAr, xB, xBr, xC, xCr, mu, lv, out);
}

// round 15
// speedup vs baseline: 1.0303x; 1.0056x over previous
#include <cuda_runtime.h>
#include <math.h>
#include <stdint.h>

#define B 16384
#define C 100
#define D 512
#define Z 128
#define BETA 50000000.0
#define EPSF 1e-8f

#define GRID        296          // 2 CTAs per SM
#define THREADS     416          // 12 consumer warps + 1 producer warp
#define NCONS       12
#define RPS         2            // rows per stage
#define NSTAGE      (B / RPS)    // 8192
#define NBUF        3

// stage layout in floats
#define OFF_TUBE(pair, al) (((pair) * 2 + (al)) * (RPS * D))   // 8 x 1024 floats
#define OFF_MU   8192
#define OFF_LV   8448
#define OFF_F    8704
#define OFF_LB   8904
#define STAGE_FLOATS 9104
#define STAGE_BYTES  (STAGE_FLOATS * 4)          // 36416
// barriers: full[0..2] then empty[0..2]
#define SMEM_BYTES   (NBUF * STAGE_BYTES + 64)   // 109312 -> 2 CTAs/SM

__device__ double g_acc[3] = {0.0, 0.0, 0.0};
__device__ unsigned g_count = 0u;

__device__ __forceinline__ uint32_t smem_u32(const void* p) {
    uint32_t a;
    asm("{ .reg .u64 t; cvta.to.shared.u64 t, %1; cvt.u32.u64 %0, t; }" : "=r"(a) : "l"(p));
    return a;
}

__device__ __forceinline__ void bulk_cp(uint32_t dst, const void* src, uint32_t bytes, uint32_t bar) {
    asm volatile("cp.async.bulk.shared::cluster.global.mbarrier::complete_tx::bytes [%0], [%1], %2, [%3];"
                 :: "r"(dst), "l"(src), "r"(bytes), "r"(bar) : "memory");
}

__device__ __forceinline__ void mbar_wait(uint32_t bar, uint32_t parity) {
    uint32_t done;
    asm volatile("{ .reg .pred p; mbarrier.try_wait.parity.acquire.cta.shared::cta.b64 p, [%1], %2; selp.b32 %0, 1, 0, p; }"
                 : "=r"(done) : "r"(bar), "r"(parity) : "memory");
    if (!done) {
        asm volatile("{ .reg .pred P1; WL%=: mbarrier.try_wait.parity.acquire.cta.shared::cta.b64 P1, [%0], %1, 0x989680; @P1 bra.uni WD%=; bra.uni WL%=; WD%=: }"
                     :: "r"(bar), "r"(parity) : "memory");
    }
}

__device__ __forceinline__ void mbar_arrive(uint32_t bar) {
    asm volatile("mbarrier.arrive.release.cta.shared::cta.b64 _, [%0];" :: "r"(bar) : "memory");
}

__device__ __forceinline__ float warp_sum(float v) {
#pragma unroll
    for (int o = 16; o; o >>= 1) v += __shfl_xor_sync(0xffffffffu, v, o);
    return v;
}

__device__ __forceinline__ float tube_scalar(float dot, float pp, float gg) {
    float p = sqrtf(pp);
    float g = sqrtf(gg);
    float denom = p * g;
    float cosine = (denom == 0.f) ? 0.f : (dot / denom);
    float s_s = 1.f - cosine * cosine;
    float sine = (s_s < 0.f) ? 0.f : sqrtf((s_s <= 0.f) ? EPSF : s_s);
    float gd = (g == 0.f) ? (g + EPSF) : g;
    float pc = p * cosine;
    float r_all = pc / gd;
    float ps = p * sine;
    float ds;
    if (r_all >= 1.f)       ds = 0.5f * (ps + fabsf(g - pc));
    else if (r_all >= 0.f)  ds = ps + fabsf(g - pc);
    else                    ds = 1.5f * fabsf(pc - g - ps);
    return -__logf(tanhf(1.f / ds));   // ds==0 -> inf -> tanh=1 -> 0, matches jax
}

extern __shared__ float smem[];

__device__ __forceinline__ void issue_stage(
    int s, uint32_t dst, uint32_t bar,
    const float* const* atts, const float* const* labs,
    const float* mu, const float* lv, const float* fusion, const float* labels)
{
    asm volatile("mbarrier.arrive.expect_tx.shared.b64 _, [%0], %1;"
                 :: "r"(bar), "r"((uint32_t)STAGE_BYTES) : "memory");
#pragma unroll
    for (int j = 0; j < 4; j++) {
        bulk_cp(dst + OFF_TUBE(j, 0) * 4, atts[j] + (long)s * (RPS * D), RPS * D * 4, bar);
        bulk_cp(dst + OFF_TUBE(j, 1) * 4, labs[j] + (long)s * (RPS * D), RPS * D * 4, bar);
    }
    bulk_cp(dst + OFF_MU * 4, mu     + (long)s * (RPS * Z), RPS * Z * 4, bar);
    bulk_cp(dst + OFF_LV * 4, lv     + (long)s * (RPS * Z), RPS * Z * 4, bar);
    bulk_cp(dst + OFF_F  * 4, fusion + (long)s * (RPS * C), RPS * C * 4, bar);
    bulk_cp(dst + OFF_LB * 4, labels + (long)s * (RPS * C), RPS * C * 4, bar);
}

__global__ void __launch_bounds__(THREADS, 2)
loss_kernel(const float* __restrict__ fusion,
            const float* __restrict__ comple,
            const float* __restrict__ labels,
            const float* __restrict__ lab_enc,
            const float* __restrict__ xA,  const float* __restrict__ xAr,
            const float* __restrict__ xB,  const float* __restrict__ xBr,
            const float* __restrict__ xC,  const float* __restrict__ xCr,
            const float* __restrict__ mu,  const float* __restrict__ lv,
            float* __restrict__ out)
{
    const int tid  = threadIdx.x;
    const int warp = tid >> 5;
    const int lane = tid & 31;
    const int bid  = blockIdx.x;

    const float* atts[4] = { xAr, xBr, xCr, comple };
    const float* labs[4] = { xA,  xB,  xC,  lab_enc };

    const uint32_t smem_base  = smem_u32(smem);
    const uint32_t full_base  = smem_base + NBUF * STAGE_BYTES;
    const uint32_t empty_base = full_base + NBUF * 8;

    if (tid == 0) {
#pragma unroll
        for (int k = 0; k < NBUF; k++) {
            asm volatile("mbarrier.init.shared.b64 [%0], 1;"  :: "r"(full_base  + k * 8) : "memory");
            asm volatile("mbarrier.init.shared.b64 [%0], %1;" :: "r"(empty_base + k * 8), "r"(NCONS) : "memory");
        }
        asm volatile("fence.proxy.async.shared::cta;" ::: "memory");
    }
    __syncthreads();

    const int nIter = (NSTAGE - bid + GRID - 1) / GRID;   // 27 or 28, >= NBUF

    float tube = 0.f, ce = 0.f, kl = 0.f;

    if (warp == NCONS) {
        // ---------------- producer warp ----------------
        if (lane == 0) {
#pragma unroll
            for (int k = 0; k < NBUF; k++)
                issue_stage(bid + k * GRID, smem_base + k * STAGE_BYTES, full_base + k * 8,
                            atts, labs, mu, lv, fusion, labels);
            for (int nx = NBUF; nx < nIter; nx++) {
                const int buf = nx % NBUF;
                const uint32_t parity = ((nx / NBUF) - 1) & 1;
                mbar_wait(empty_base + buf * 8, parity);
                asm volatile("fence.proxy.async.shared::cta;" ::: "memory");
                issue_stage(bid + nx * GRID, smem_base + buf * STAGE_BYTES, full_base + buf * 8,
                            atts, labs, mu, lv, fusion, labels);
            }
        }
    } else {
        // ---------------- consumer warps (0..11): exactly 1 task per stage ----------------
        int buf = 0;
        unsigned parity = 0;
        for (int it = 0; it < nIter; it++) {
            mbar_wait(full_base + buf * 8, parity);
            const float* bufp = smem + buf * STAGE_FLOATS;

            if (warp < 8) {
                const int row = warp >> 2, pair = warp & 3;
                const float4* a4 = (const float4*)(bufp + OFF_TUBE(pair, 0) + row * D);
                const float4* g4 = (const float4*)(bufp + OFF_TUBE(pair, 1) + row * D);
                float dot = 0.f, pp = 0.f, gg = 0.f;
#pragma unroll
                for (int i = 0; i < 4; i++) {
                    float4 a = a4[lane + 32 * i];
                    float4 g = g4[lane + 32 * i];
                    dot += a.x * g.x + a.y * g.y + a.z * g.z + a.w * g.w;
                    pp  += a.x * a.x + a.y * a.y + a.z * a.z + a.w * a.w;
                    gg  += g.x * g.x + g.y * g.y + g.z * g.z + g.w * g.w;
                }
                dot = warp_sum(dot);
                pp  = warp_sum(pp);
                gg  = warp_sum(gg);
                tube += tube_scalar(dot, pp, gg);
            } else if (warp < 10) {
                const int row = warp - 8;
                float4 m = ((const float4*)(bufp + OFF_MU + row * Z))[lane];
                float4 l = ((const float4*)(bufp + OFF_LV + row * Z))[lane];
                float k = (1.f + l.x - m.x * m.x - __expf(l.x))
                        + (1.f + l.y - m.y * m.y - __expf(l.y))
                        + (1.f + l.z - m.z * m.z - __expf(l.z))
                        + (1.f + l.w - m.w * m.w - __expf(l.w));
                kl += warp_sum(k);
            } else {
                const int row = warp - 10;
                const float* f  = bufp + OFF_F  + row * C;
                const float* lb = bufp + OFF_LB + row * C;
                float fmax = -INFINITY, lmax = -INFINITY;
                int lidx = 0x7fffffff;
#pragma unroll
                for (int q = 0; q < 4; q++) {
                    int i = lane + 32 * q;
                    if (i < C) {
                        float fv  = f[i];
                        float lvv = lb[i];
                        fmax = fmaxf(fmax, fv);
                        if (lvv > lmax || (lvv == lmax && i < lidx)) { lmax = lvv; lidx = i; }
                    }
                }
#pragma unroll
                for (int o = 16; o; o >>= 1) {
                    fmax = fmaxf(fmax, __shfl_xor_sync(0xffffffffu, fmax, o));
                    float ol = __shfl_xor_sync(0xffffffffu, lmax, o);
                    int   oi = __shfl_xor_sync(0xffffffffu, lidx, o);
                    if (ol > lmax || (ol == lmax && oi < lidx)) { lmax = ol; lidx = oi; }
                }
                float se = 0.f;
#pragma unroll
                for (int q = 0; q < 4; q++) {
                    int i = lane + 32 * q;
                    if (i < C) se += __expf(f[i] - fmax);
                }
                se = warp_sum(se);
                ce += -(f[lidx] - fmax - __logf(se));
            }

            __syncwarp();
            if (lane == 0) mbar_arrive(empty_base + buf * 8);   // free this buffer

            if (++buf == NBUF) { buf = 0; parity ^= 1u; }
        }
    }

    // ---- block reduce + last-block finalize ----
    __shared__ float sT[13], sC[13], sK[13];
    if (lane == 0) { sT[warp] = tube; sC[warp] = ce; sK[warp] = kl; }
    __syncthreads();
    if (tid == 0) {
        float t = 0.f, c = 0.f, k = 0.f;
#pragma unroll
        for (int i = 0; i < NCONS; i++) { t += sT[i]; c += sC[i]; k += sK[i]; }
        atomicAdd(&g_acc[0], (double)t);
        atomicAdd(&g_acc[1], (double)c);
        atomicAdd(&g_acc[2], (double)k);
        __threadfence();
        unsigned prev = atomicAdd(&g_count, 1u);
        if (prev == gridDim.x - 1) {
            __threadfence();
            double tubeS = g_acc[0] / (double)B;                         // ALPHA = 1
            double ceS   = g_acc[1] / (double)B;
            double klS   = -0.5 * BETA * (g_acc[2] / ((double)B * (double)Z));
            out[0] = (float)(tubeS + ceS + klS);
            g_acc[0] = 0.0; g_acc[1] = 0.0; g_acc[2] = 0.0;
            g_count = 0u;
            __threadfence();
        }
    }
}

extern "C" void kernel_launch(void* const* d_in, const int* in_sizes, int n_in,
                              void* d_out, int out_size) {
    const float* fusion  = (const float*)d_in[0];
    const float* comple  = (const float*)d_in[1];
    const float* labels  = (const float*)d_in[2];
    const float* lab_enc = (const float*)d_in[3];
    const float* xA      = (const float*)d_in[4];
    const float* xAr     = (const float*)d_in[5];
    const float* xB      = (const float*)d_in[6];
    const float* xBr     = (const float*)d_in[7];
    const float* xC      = (const float*)d_in[8];
    const float* xCr     = (const float*)d_in[9];
    const float* mu      = (const float*)d_in[10];
    const float* lv      = (const float*)d_in[11];
    float* out = (float*)d_out;

    static int configured = 0;
    if (!configured) {
        cudaFuncSetAttribute(loss_kernel, cudaFuncAttributeMaxDynamicSharedMemorySize, SMEM_BYTES);
        configured = 1;
    }
    loss_kernel<<<GRID, THREADS, SMEM_BYTES>>>(fusion, comple, labels, lab_enc,
                                               xA, xAr, xB, xBr, xC, xCr, mu, lv, out);
}

// round 16
// speedup vs baseline: 1.0387x; 1.0081x over previous
#include <cuda_runtime.h>
#include <math.h>
#include <stdint.h>

#define B 16384
#define C 100
#define D 512
#define Z 128
#define BETA 50000000.0
#define EPSF 1e-8f

#define GRID        148
#define THREADS     800          // 24 consumer warps + 1 producer warp
#define NCONS       24
#define RPS         4            // rows per stage
#define NSTAGE      (B / RPS)    // 4096
#define NBUF        3
#define NGRP        3            // full-barrier groups per stage

// stage layout in floats
#define OFF_TUBE(pair, al) (((pair) * 2 + (al)) * (RPS * D))   // 8 x 2048 floats
#define OFF_MU   16384
#define OFF_LV   16896
#define OFF_F    17408
#define OFF_LB   17808
#define STAGE_FLOATS 18208
#define STAGE_BYTES  (STAGE_FLOATS * 4)          // 72832
#define G01_BYTES    (4 * RPS * D * 4)           // 32768 (2 pairs = 4 arrays)
#define G2_BYTES     (STAGE_BYTES - 2 * G01_BYTES) // 7296
// barriers: full[buf][grp] (9) then empty[buf] (3)
#define SMEM_BYTES   (NBUF * STAGE_BYTES + 128)

__device__ double g_acc[3] = {0.0, 0.0, 0.0};
__device__ unsigned g_count = 0u;

__device__ __forceinline__ uint32_t smem_u32(const void* p) {
    uint32_t a;
    asm("{ .reg .u64 t; cvta.to.shared.u64 t, %1; cvt.u32.u64 %0, t; }" : "=r"(a) : "l"(p));
    return a;
}

__device__ __forceinline__ void bulk_cp(uint32_t dst, const void* src, uint32_t bytes, uint32_t bar) {
    asm volatile("cp.async.bulk.shared::cluster.global.mbarrier::complete_tx::bytes [%0], [%1], %2, [%3];"
                 :: "r"(dst), "l"(src), "r"(bytes), "r"(bar) : "memory");
}

__device__ __forceinline__ void mbar_wait(uint32_t bar, uint32_t parity) {
    uint32_t done;
    asm volatile("{ .reg .pred p; mbarrier.try_wait.parity.acquire.cta.shared::cta.b64 p, [%1], %2; selp.b32 %0, 1, 0, p; }"
                 : "=r"(done) : "r"(bar), "r"(parity) : "memory");
    if (!done) {
        asm volatile("{ .reg .pred P1; WL%=: mbarrier.try_wait.parity.acquire.cta.shared::cta.b64 P1, [%0], %1, 0x989680; @P1 bra.uni WD%=; bra.uni WL%=; WD%=: }"
                     :: "r"(bar), "r"(parity) : "memory");
    }
}

__device__ __forceinline__ void mbar_arrive(uint32_t bar) {
    asm volatile("mbarrier.arrive.release.cta.shared::cta.b64 _, [%0];" :: "r"(bar) : "memory");
}

__device__ __forceinline__ void mbar_expect(uint32_t bar, uint32_t bytes) {
    asm volatile("mbarrier.arrive.expect_tx.shared.b64 _, [%0], %1;"
                 :: "r"(bar), "r"(bytes) : "memory");
}

__device__ __forceinline__ float warp_sum(float v) {
#pragma unroll
    for (int o = 16; o; o >>= 1) v += __shfl_xor_sync(0xffffffffu, v, o);
    return v;
}

__device__ __forceinline__ float tube_scalar(float dot, float pp, float gg) {
    float p = sqrtf(pp);
    float g = sqrtf(gg);
    float denom = p * g;
    float cosine = (denom == 0.f) ? 0.f : (dot / denom);
    float s_s = 1.f - cosine * cosine;
    float sine = (s_s < 0.f) ? 0.f : sqrtf((s_s <= 0.f) ? EPSF : s_s);
    float gd = (g == 0.f) ? (g + EPSF) : g;
    float pc = p * cosine;
    float r_all = pc / gd;
    float ps = p * sine;
    float ds;
    if (r_all >= 1.f)       ds = 0.5f * (ps + fabsf(g - pc));
    else if (r_all >= 0.f)  ds = ps + fabsf(g - pc);
    else                    ds = 1.5f * fabsf(pc - g - ps);
    return -__logf(tanhf(1.f / ds));   // ds==0 -> inf -> tanh=1 -> 0, matches jax
}

extern __shared__ float smem[];

// issue one stage: 3 barrier groups (g0: pairs 0-1, g1: pairs 2-3, g2: small)
__device__ __forceinline__ void issue_stage(
    int s, uint32_t dst, uint32_t fbar0,
    const float* const* atts, const float* const* labs,
    const float* mu, const float* lv, const float* fusion, const float* labels)
{
    mbar_expect(fbar0,      G01_BYTES);
    mbar_expect(fbar0 + 8,  G01_BYTES);
    mbar_expect(fbar0 + 16, G2_BYTES);
#pragma unroll
    for (int j = 0; j < 2; j++) {
        bulk_cp(dst + OFF_TUBE(j, 0) * 4, atts[j] + (long)s * (RPS * D), RPS * D * 4, fbar0);
        bulk_cp(dst + OFF_TUBE(j, 1) * 4, labs[j] + (long)s * (RPS * D), RPS * D * 4, fbar0);
    }
#pragma unroll
    for (int j = 2; j < 4; j++) {
        bulk_cp(dst + OFF_TUBE(j, 0) * 4, atts[j] + (long)s * (RPS * D), RPS * D * 4, fbar0 + 8);
        bulk_cp(dst + OFF_TUBE(j, 1) * 4, labs[j] + (long)s * (RPS * D), RPS * D * 4, fbar0 + 8);
    }
    bulk_cp(dst + OFF_MU * 4, mu     + (long)s * (RPS * Z), RPS * Z * 4, fbar0 + 16);
    bulk_cp(dst + OFF_LV * 4, lv     + (long)s * (RPS * Z), RPS * Z * 4, fbar0 + 16);
    bulk_cp(dst + OFF_F  * 4, fusion + (long)s * (RPS * C), RPS * C * 4, fbar0 + 16);
    bulk_cp(dst + OFF_LB * 4, labels + (long)s * (RPS * C), RPS * C * 4, fbar0 + 16);
}

__global__ void __launch_bounds__(THREADS, 1)
loss_kernel(const float* __restrict__ fusion,
            const float* __restrict__ comple,
            const float* __restrict__ labels,
            const float* __restrict__ lab_enc,
            const float* __restrict__ xA,  const float* __restrict__ xAr,
            const float* __restrict__ xB,  const float* __restrict__ xBr,
            const float* __restrict__ xC,  const float* __restrict__ xCr,
            const float* __restrict__ mu,  const float* __restrict__ lv,
            float* __restrict__ out)
{
    const int tid  = threadIdx.x;
    const int warp = tid >> 5;
    const int lane = tid & 31;
    const int bid  = blockIdx.x;

    const float* atts[4] = { xAr, xBr, xCr, comple };
    const float* labs[4] = { xA,  xB,  xC,  lab_enc };

    const uint32_t smem_base  = smem_u32(smem);
    const uint32_t full_base  = smem_base + NBUF * STAGE_BYTES;    // full[buf*NGRP+g]
    const uint32_t empty_base = full_base + NBUF * NGRP * 8;       // empty[buf]

    if (tid == 0) {
#pragma unroll
        for (int k = 0; k < NBUF; k++) {
#pragma unroll
            for (int g = 0; g < NGRP; g++)
                asm volatile("mbarrier.init.shared.b64 [%0], 1;"  :: "r"(full_base + (k * NGRP + g) * 8) : "memory");
            asm volatile("mbarrier.init.shared.b64 [%0], %1;" :: "r"(empty_base + k * 8), "r"(NCONS) : "memory");
        }
        asm volatile("fence.proxy.async.shared::cta;" ::: "memory");
    }
    __syncthreads();

    const int nIter = (NSTAGE - bid + GRID - 1) / GRID;   // 27 or 28, >= NBUF

    float tube = 0.f, ce = 0.f, kl = 0.f;

    if (warp == NCONS) {
        // ---------------- producer warp ----------------
        if (lane == 0) {
#pragma unroll
            for (int k = 0; k < NBUF; k++)
                issue_stage(bid + k * GRID, smem_base + k * STAGE_BYTES,
                            full_base + k * NGRP * 8,
                            atts, labs, mu, lv, fusion, labels);
            for (int nx = NBUF; nx < nIter; nx++) {
                const int buf = nx % NBUF;
                const uint32_t parity = ((nx / NBUF) - 1) & 1;
                mbar_wait(empty_base + buf * 8, parity);
                asm volatile("fence.proxy.async.shared::cta;" ::: "memory");
                issue_stage(bid + nx * GRID, smem_base + buf * STAGE_BYTES,
                            full_base + buf * NGRP * 8,
                            atts, labs, mu, lv, fusion, labels);
            }
        }
    } else {
        // ---------------- consumer warps (0..23): 1 task per stage, group-scoped waits ----------------
        const int mygrp = (warp < 8) ? 0 : (warp < 16) ? 1 : 2;
        int buf = 0;
        unsigned parity = 0;
        for (int it = 0; it < nIter; it++) {
            mbar_wait(full_base + (buf * NGRP + mygrp) * 8, parity);
            const float* bufp = smem + buf * STAGE_FLOATS;

            if (warp < 16) {
                const int row = warp >> 2, pair = warp & 3;
                const float4* a4 = (const float4*)(bufp + OFF_TUBE(pair, 0) + row * D);
                const float4* g4 = (const float4*)(bufp + OFF_TUBE(pair, 1) + row * D);
                float dot = 0.f, pp = 0.f, gg = 0.f;
#pragma unroll
                for (int i = 0; i < 4; i++) {
                    float4 a = a4[lane + 32 * i];
                    float4 g = g4[lane + 32 * i];
                    dot += a.x * g.x + a.y * g.y + a.z * g.z + a.w * g.w;
                    pp  += a.x * a.x + a.y * a.y + a.z * a.z + a.w * a.w;
                    gg  += g.x * g.x + g.y * g.y + g.z * g.z + g.w * g.w;
                }
                dot = warp_sum(dot);
                pp  = warp_sum(pp);
                gg  = warp_sum(gg);
                tube += tube_scalar(dot, pp, gg);
            } else if (warp < 20) {
                const int row = warp - 16;
                float4 m = ((const float4*)(bufp + OFF_MU + row * Z))[lane];
                float4 l = ((const float4*)(bufp + OFF_LV + row * Z))[lane];
                float k = (1.f + l.x - m.x * m.x - __expf(l.x))
                        + (1.f + l.y - m.y * m.y - __expf(l.y))
                        + (1.f + l.z - m.z * m.z - __expf(l.z))
                        + (1.f + l.w - m.w * m.w - __expf(l.w));
                kl += warp_sum(k);
            } else {
                const int row = warp - 20;
                const float* f  = bufp + OFF_F  + row * C;
                const float* lb = bufp + OFF_LB + row * C;
                float fmax = -INFINITY, lmax = -INFINITY;
                int lidx = 0x7fffffff;
#pragma unroll
                for (int q = 0; q < 4; q++) {
                    int i = lane + 32 * q;
                    if (i < C) {
                        float fv  = f[i];
                        float lvv = lb[i];
                        fmax = fmaxf(fmax, fv);
                        if (lvv > lmax || (lvv == lmax && i < lidx)) { lmax = lvv; lidx = i; }
                    }
                }
#pragma unroll
                for (int o = 16; o; o >>= 1) {
                    fmax = fmaxf(fmax, __shfl_xor_sync(0xffffffffu, fmax, o));
                    float ol = __shfl_xor_sync(0xffffffffu, lmax, o);
                    int   oi = __shfl_xor_sync(0xffffffffu, lidx, o);
                    if (ol > lmax || (ol == lmax && oi < lidx)) { lmax = ol; lidx = oi; }
                }
                float se = 0.f;
#pragma unroll
                for (int q = 0; q < 4; q++) {
                    int i = lane + 32 * q;
                    if (i < C) se += __expf(f[i] - fmax);
                }
                se = warp_sum(se);
                ce += -(f[lidx] - fmax - __logf(se));
            }

            __syncwarp();
            if (lane == 0) mbar_arrive(empty_base + buf * 8);   // free this buffer

            if (++buf == NBUF) { buf = 0; parity ^= 1u; }
        }
    }

    // ---- block reduce + last-block finalize ----
    __shared__ float sT[25], sC[25], sK[25];
    if (lane == 0) { sT[warp] = tube; sC[warp] = ce; sK[warp] = kl; }
    __syncthreads();
    if (tid == 0) {
        float t = 0.f, c = 0.f, k = 0.f;
#pragma unroll
        for (int i = 0; i < NCONS; i++) { t += sT[i]; c += sC[i]; k += sK[i]; }
        atomicAdd(&g_acc[0], (double)t);
        atomicAdd(&g_acc[1], (double)c);
        atomicAdd(&g_acc[2], (double)k);
        __threadfence();
        unsigned prev = atomicAdd(&g_count, 1u);
        if (prev == gridDim.x - 1) {
            __threadfence();
            double tubeS = g_acc[0] / (double)B;                         // ALPHA = 1
            double ceS   = g_acc[1] / (double)B;
            double klS   = -0.5 * BETA * (g_acc[2] / ((double)B * (double)Z));
            out[0] = (float)(tubeS + ceS + klS);
            g_acc[0] = 0.0; g_acc[1] = 0.0; g_acc[2] = 0.0;
            g_count = 0u;
            __threadfence();
        }
    }
}

extern "C" void kernel_launch(void* const* d_in, const int* in_sizes, int n_in,
                              void* d_out, int out_size) {
    const float* fusion  = (const float*)d_in[0];
    const float* comple  = (const float*)d_in[1];
    const float* labels  = (const float*)d_in[2];
    const float* lab_enc = (const float*)d_in[3];
    const float* xA      = (const float*)d_in[4];
    const float* xAr     = (const float*)d_in[5];
    const float* xB      = (const float*)d_in[6];
    const float* xBr     = (const float*)d_in[7];
    const float* xC      = (const float*)d_in[8];
    const float* xCr     = (const float*)d_in[9];
    const float* mu      = (const float*)d_in[10];
    const float* lv      = (const float*)d_in[11];
    float* out = (float*)d_out;

    static int configured = 0;
    if (!configured) {
        cudaFuncSetAttribute(loss_kernel, cudaFuncAttributeMaxDynamicSharedMemorySize, SMEM_BYTES);
        configured = 1;
    }
    loss_kernel<<<GRID, THREADS, SMEM_BYTES>>>(fusion, comple, labels, lab_enc,
                                               xA, xAr, xB, xBr, xC, xCr, mu, lv, out);
}